// round 17
// baseline (speedup 1.0000x reference)
#include <cuda_runtime.h>
#include <cuda_fp16.h>
#include <cstdint>
#include <math.h>

// Problem constants
#define Bc   2
#define Tc   8192
#define Hc   8
#define Dc   128
#define HIDc 1024
#define NCc  128          // T / CHUNK
#define Fc   256          // hedgehog feature dim (2*DQK)
#define MTOT (Bc*Tc)      // 16384 tokens

// ---------------------------------------------------------------------------
// Scratch (device globals — no allocations allowed)
// ---------------------------------------------------------------------------
__device__ __half g_xh  [(size_t)MTOT*HIDc];      // 32 MB
__device__ __half g_wvh [HIDc*HIDc];
__device__ __half g_woh [HIDc*HIDc];
__device__ __half g_wq2 [HIDc*HIDc];              // folded fmq @ Wq (per head)
__device__ __half g_wk2 [HIDc*HIDc];              // folded fmk @ Wk
__device__ __half g_v   [(size_t)MTOT*HIDc];
__device__ __half g_qf  [(size_t)MTOT*Hc*Fc];     // 64 MB (pre-scaled)
__device__ __half g_kf  [(size_t)MTOT*Hc*Fc];     // 64 MB
__device__ __half g_s   [(size_t)Bc*Hc*NCc*Fc*Dc]; // 128 MB exclusive prefix (fp16)
__device__ __half g_oh  [(size_t)MTOT*HIDc];      // attention out (unnormalized)
__device__ float  g_prs [MTOT*Hc];                // per-(token,head) partial sumsq

// ---------------------------------------------------------------------------
// Helpers
// ---------------------------------------------------------------------------
__device__ __forceinline__ uint32_t smem_u32(const void* p) {
    uint32_t a;
    asm("{ .reg .u64 t; cvta.to.shared.u64 t, %1; cvt.u32.u64 %0, t; }" : "=r"(a) : "l"(p));
    return a;
}
__device__ __forceinline__ uint32_t pack2(float lo, float hi) {
    __half2 h = __floats2half2_rn(lo, hi);
    return *reinterpret_cast<uint32_t*>(&h);
}
__device__ __forceinline__ void mma_f16(float* c, const uint32_t* a, const uint32_t* b) {
    asm volatile(
        "mma.sync.aligned.m16n8k16.row.col.f32.f16.f16.f32 "
        "{%0,%1,%2,%3}, {%4,%5,%6,%7}, {%8,%9}, {%0,%1,%2,%3};"
        : "+f"(c[0]), "+f"(c[1]), "+f"(c[2]), "+f"(c[3])
        : "r"(a[0]), "r"(a[1]), "r"(a[2]), "r"(a[3]), "r"(b[0]), "r"(b[1]));
}
#define LDSM4(r, addr) \
    asm volatile("ldmatrix.sync.aligned.m8n8.x4.shared.b16 {%0,%1,%2,%3}, [%4];" \
        : "=r"((r)[0]), "=r"((r)[1]), "=r"((r)[2]), "=r"((r)[3]) : "r"(addr))
#define LDSM4T(r, addr) \
    asm volatile("ldmatrix.sync.aligned.m8n8.x4.trans.shared.b16 {%0,%1,%2,%3}, [%4];" \
        : "=r"((r)[0]), "=r"((r)[1]), "=r"((r)[2]), "=r"((r)[3]) : "r"(addr))
__device__ __forceinline__ void cp16(uint32_t dst, const void* src) {
    asm volatile("cp.async.cg.shared.global [%0], [%1], 16;" :: "r"(dst), "l"(src) : "memory");
}
#define CP_COMMIT() asm volatile("cp.async.commit_group;" ::: "memory")
#define CP_WAIT(n)  asm volatile("cp.async.wait_group %0;" :: "n"(n) : "memory")

// ---------------------------------------------------------------------------
// Merged f32 -> f16 conversion: blocks [0,8192) -> x, [8192,8704) -> Wv,
// [8704,9216) -> Wo.
// ---------------------------------------------------------------------------
__global__ __launch_bounds__(256) void conv_all(
    const float* __restrict__ x, const float* __restrict__ Wv,
    const float* __restrict__ Wo)
{
    int bidx = blockIdx.x;
    const float* s;
    __half* d;
    int base;
    if (bidx < 8192)      { s = x;  d = g_xh;  base = bidx; }
    else if (bidx < 8704) { s = Wv; d = g_wvh; base = bidx - 8192; }
    else                  { s = Wo; d = g_woh; base = bidx - 8704; }
    int i = (base * 256 + threadIdx.x) * 8;
    float4 a = *(const float4*)(s + i), b = *(const float4*)(s + i + 4);
    *(uint4*)(d + i) = make_uint4(pack2(a.x, a.y), pack2(a.z, a.w),
                                  pack2(b.x, b.y), pack2(b.z, b.w));
}

// ---------------------------------------------------------------------------
// Fold: W2[h*128+i, c] = sum_j fm[i,j] * W[h*128+j, c]   (reads f32 W directly)
// ---------------------------------------------------------------------------
#define FSKP 136
#define FD_A 0
#define FD_B (128*FSKP*2)               // 34816
#define FOLD_SMEM (2*128*FSKP*2)        // 69632

__global__ __launch_bounds__(256) void fold_w(
    const float* __restrict__ fmq, const float* __restrict__ fmk,
    const float* __restrict__ Wq,  const float* __restrict__ Wk)
{
    const int z = blockIdx.z;
    const float* fm = z ? fmk : fmq;
    const float* Wf = z ? Wk : Wq;
    __half* W2 = z ? g_wk2 : g_wq2;

    extern __shared__ char smc[];
    const uint32_t sb = smem_u32(smc);
    const int tid = threadIdx.x, wid = tid >> 5, lane = tid & 31;
    const int wm = wid & 3, wn = wid >> 2;
    const int qr = lane >> 2, qc = lane & 3;
    const int ct = blockIdx.x, h = blockIdx.y;

#pragma unroll
    for (int it = 0; it < 16; it++) {
        int e = tid + it * 256;
        int r = e >> 5, c4 = e & 31;
        float4 f = *(const float4*)(fm + r * 128 + c4 * 4);
        *(uint2*)(smc + FD_A + ((uint32_t)r * FSKP + c4 * 4) * 2) =
            make_uint2(pack2(f.x, f.y), pack2(f.z, f.w));
    }
#pragma unroll
    for (int it = 0; it < 16; it++) {
        int e = tid + it * 256;
        int r = e >> 5, c4 = e & 31;
        float4 f = *(const float4*)(Wf + (size_t)(h * 128 + r) * 1024 + ct * 128 + c4 * 4);
        *(uint2*)(smc + FD_B + ((uint32_t)r * FSKP + c4 * 4) * 2) =
            make_uint2(pack2(f.x, f.y), pack2(f.z, f.w));
    }
    __syncthreads();

    float acc[2][8][4];
#pragma unroll
    for (int mf = 0; mf < 2; mf++)
#pragma unroll
        for (int nf = 0; nf < 8; nf++)
#pragma unroll
            for (int i = 0; i < 4; i++) acc[mf][nf][i] = 0.f;

    const uint32_t a_off = FD_A + (uint32_t)(wm*32 + (lane&7) + ((lane>>3)&1)*8) * (FSKP*2)
                         + (lane>>4)*16;
    const uint32_t cb = (lane & 7) + ((lane >> 3) & 1) * 8;
    const uint32_t nb = (lane >> 4) * 8;

#pragma unroll
    for (int ks = 0; ks < 8; ks++) {
        uint32_t a[2][4];
        LDSM4(a[0], sb + a_off + ks * 32);
        LDSM4(a[1], sb + a_off + 16 * FSKP * 2 + ks * 32);
#pragma unroll
        for (int np = 0; np < 4; np++) {
            uint32_t b[4];
            LDSM4T(b, sb + FD_B + ((ks*16 + cb) * FSKP + wn*64 + np*16 + nb) * 2);
            mma_f16(acc[0][2*np],   a[0], b);
            mma_f16(acc[0][2*np+1], a[0], b + 2);
            mma_f16(acc[1][2*np],   a[1], b);
            mma_f16(acc[1][2*np+1], a[1], b + 2);
        }
    }

#pragma unroll
    for (int mf = 0; mf < 2; mf++) {
        const int i0 = h * 128 + wm * 32 + mf * 16 + qr;
#pragma unroll
        for (int nf = 0; nf < 8; nf++) {
            const int c0 = ct * 128 + wn * 64 + nf * 8 + qc * 2;
            *(uint32_t*)&W2[(size_t)i0 * 1024 + c0] = pack2(acc[mf][nf][0], acc[mf][nf][1]);
            *(uint32_t*)&W2[(size_t)(i0 + 8) * 1024 + c0] = pack2(acc[mf][nf][2], acc[mf][nf][3]);
        }
    }
}

// ---------------------------------------------------------------------------
// GEMM core macros (CTA 128x128, BK=64, 3-stage, 8 warps 4x2, 2 CTAs/SM)
// ---------------------------------------------------------------------------
#define SKP_B   144                   // 64 halves + 8 pad = 144 bytes per row
#define GA_B    (128*SKP_B)           // 18432
#define GSTG    (2*GA_B)              // 36864
#define GEMM_SMEM (3*GSTG)            // 110592

#define GEMM_MAIN(X, W)                                                    \
    const int pr = tid >> 3, pp = tid & 7;                                 \
    const __half* Xp = (X) + (size_t)(m0 + pr) * 1024 + pp * 8;            \
    const __half* Wp = (W) + (size_t)(n0 + pr) * 1024 + pp * 8;            \
    const uint32_t a_off = (uint32_t)(wm*32 + (lane&7) + ((lane>>3)&1)*8) * SKP_B \
                         + (lane>>4)*16;                                   \
    const uint32_t b_off = (uint32_t)(wn*64 + (lane>>4)*8 + (lane&7)) * SKP_B \
                         + ((lane>>3)&1)*16;                               \
    float acc[2][8][4];                                                    \
    _Pragma("unroll")                                                      \
    for (int mf = 0; mf < 2; mf++)                                         \
        _Pragma("unroll")                                                  \
        for (int nf = 0; nf < 8; nf++)                                     \
            _Pragma("unroll")                                              \
            for (int i = 0; i < 4; i++) acc[mf][nf][i] = 0.f;              \
    LOAD_STAGE(0, 0); CP_COMMIT();                                         \
    LOAD_STAGE(1, 1); CP_COMMIT();                                         \
    for (int kt = 0; kt < 16; kt++) {                                      \
        const int st = kt % 3;                                             \
        CP_WAIT(1);                                                        \
        __syncthreads();                                                   \
        const uint32_t As = sb + st * GSTG, Bs = As + GA_B;                \
        _Pragma("unroll")                                                  \
        for (int ks = 0; ks < 4; ks++) {                                   \
            uint32_t a[2][4];                                              \
            LDSM4(a[0], As + a_off + ks * 32);                             \
            LDSM4(a[1], As + a_off + 16 * SKP_B + ks * 32);                \
            _Pragma("unroll")                                              \
            for (int np = 0; np < 4; np++) {                               \
                uint32_t b[4];                                             \
                LDSM4(b, Bs + b_off + np * (16 * SKP_B) + ks * 32);        \
                mma_f16(acc[0][2*np],   a[0], b);                          \
                mma_f16(acc[0][2*np+1], a[0], b + 2);                      \
                mma_f16(acc[1][2*np],   a[1], b);                          \
                mma_f16(acc[1][2*np+1], a[1], b + 2);                      \
            }                                                              \
        }                                                                  \
        if (kt + 2 < 16) LOAD_STAGE(kt + 2, (kt + 2) % 3);                 \
        CP_COMMIT();                                                       \
    }

#define LOAD_STAGE(kt, st) {                                              \
    uint32_t base = sb + (st) * GSTG;                                     \
    const __half* xk = Xp + (kt) * 64;                                    \
    const __half* wk = Wp + (kt) * 64;                                    \
    _Pragma("unroll")                                                     \
    for (int i = 0; i < 4; i++) {                                         \
        uint32_t so = (uint32_t)(pr + 32*i) * SKP_B + pp * 16;            \
        cp16(base + so, xk + (size_t)(32*i) * 1024);                      \
        cp16(base + GA_B + so, wk + (size_t)(32*i) * 1024);               \
    } }

// ---------------------------------------------------------------------------
// Fused QKV GEMM. z=0: q (softmax epilogue, scale 1/16), z=1: k (softmax),
// z=2: v (fp16 write).
// ---------------------------------------------------------------------------
__global__ __launch_bounds__(256, 2) void gemm_qkv(
    const float* __restrict__ biasq, const float* __restrict__ biask)
{
    const int z = blockIdx.z;
    const __half* W = (z == 0) ? g_wq2 : ((z == 1) ? g_wk2 : g_wvh);

    extern __shared__ char smc[];
    const uint32_t sb = smem_u32(smc);
    const int tid = threadIdx.x, wid = tid >> 5, lane = tid & 31;
    const int wm = wid & 3, wn = wid >> 2;
    const int qr = lane >> 2, qc = lane & 3;
    const int m0 = blockIdx.y * 128, n0 = blockIdx.x * 128;

    GEMM_MAIN(g_xh, W)

    if (z == 2) {
#pragma unroll
        for (int mf = 0; mf < 2; mf++) {
            const int r0 = m0 + wm * 32 + mf * 16 + qr;
#pragma unroll
            for (int nf = 0; nf < 8; nf++) {
                const int c0 = n0 + wn * 64 + nf * 8 + qc * 2;
                *(uint32_t*)&g_v[(size_t)r0 * 1024 + c0] =
                    pack2(acc[mf][nf][0], acc[mf][nf][1]);
                *(uint32_t*)&g_v[(size_t)(r0 + 8) * 1024 + c0] =
                    pack2(acc[mf][nf][2], acc[mf][nf][3]);
            }
        }
        return;
    }

    // q/k: hedgehog softmax epilogue. Reuse stage smem as f32 ys[128][132].
    __syncthreads();
    float* ys = (float*)smc;
#pragma unroll
    for (int mf = 0; mf < 2; mf++) {
        const int r0 = wm * 32 + mf * 16 + qr;
#pragma unroll
        for (int nf = 0; nf < 8; nf++) {
            const int c0 = wn * 64 + nf * 8 + qc * 2;
            *(float2*)(ys + r0 * 132 + c0) = make_float2(acc[mf][nf][0], acc[mf][nf][1]);
            *(float2*)(ys + (r0 + 8) * 132 + c0) = make_float2(acc[mf][nf][2], acc[mf][nf][3]);
        }
    }
    __syncthreads();

    const float* bias = z ? biask : biasq;
    const float scale = z ? 1.0f : 0.0625f;   // 256^-0.5 folded into qf
    __half* dst = z ? g_kf : g_qf;
    const int h = blockIdx.x;
    float4 bv = *(const float4*)(bias + lane * 4);

    for (int rr = 0; rr < 16; rr += 2) {
        const int r0 = wid * 16 + rr;
        float y[2][4], m[2];
#pragma unroll
        for (int u = 0; u < 2; u++) {
            float4 v4 = *(const float4*)(ys + (r0 + u) * 132 + lane * 4);
            y[u][0] = 2.f * (v4.x + bv.x); y[u][1] = 2.f * (v4.y + bv.y);
            y[u][2] = 2.f * (v4.z + bv.z); y[u][3] = 2.f * (v4.w + bv.w);
            m[u] = fmaxf(fmaxf(fabsf(y[u][0]), fabsf(y[u][1])),
                         fmaxf(fabsf(y[u][2]), fabsf(y[u][3])));
        }
#pragma unroll
        for (int off = 16; off >= 1; off >>= 1) {
            m[0] = fmaxf(m[0], __shfl_xor_sync(0xffffffffu, m[0], off));
            m[1] = fmaxf(m[1], __shfl_xor_sync(0xffffffffu, m[1], off));
        }
        float ep[2][4], en[2][4], zs[2] = {0.f, 0.f};
#pragma unroll
        for (int u = 0; u < 2; u++)
#pragma unroll
            for (int j = 0; j < 4; j++) {
                ep[u][j] = __expf( y[u][j] - m[u]);
                en[u][j] = __expf(-y[u][j] - m[u]);
                zs[u] += ep[u][j] + en[u][j];
            }
#pragma unroll
        for (int off = 16; off >= 1; off >>= 1) {
            zs[0] += __shfl_xor_sync(0xffffffffu, zs[0], off);
            zs[1] += __shfl_xor_sync(0xffffffffu, zs[1], off);
        }
#pragma unroll
        for (int u = 0; u < 2; u++) {
            const float inv = scale / zs[u];
            __half* drow = dst + ((size_t)(m0 + r0 + u) * Hc + h) * Fc;
            *(uint2*)(drow + lane * 4) =
                make_uint2(pack2(ep[u][0]*inv, ep[u][1]*inv),
                           pack2(ep[u][2]*inv, ep[u][3]*inv));
            *(uint2*)(drow + 128 + lane * 4) =
                make_uint2(pack2(en[u][0]*inv, en[u][1]*inv),
                           pack2(en[u][2]*inv, en[u][3]*inv));
        }
    }
}

// ---------------------------------------------------------------------------
// Wo GEMM with rmsnorm row-scale epilogue (rs computed inline from g_prs):
// out[r][c] = rs[r] * (o @ Wo^T)
// ---------------------------------------------------------------------------
__global__ __launch_bounds__(256, 2) void gemm_o(float* __restrict__ out)
{
    extern __shared__ char smc[];
    __shared__ float rs_s[128];
    const uint32_t sb = smem_u32(smc);
    const int tid = threadIdx.x, wid = tid >> 5, lane = tid & 31;
    const int wm = wid & 3, wn = wid >> 2;
    const int qr = lane >> 2, qc = lane & 3;
    const int m0 = blockIdx.y * 128, n0 = blockIdx.x * 128;

    if (tid < 128) {
        float4 a = *(const float4*)&g_prs[(size_t)(m0 + tid) * Hc];
        float4 b4 = *(const float4*)&g_prs[(size_t)(m0 + tid) * Hc + 4];
        float s = a.x + a.y + a.z + a.w + b4.x + b4.y + b4.z + b4.w;
        rs_s[tid] = rsqrtf(s * (1.f / HIDc) + 1e-5f);
    }

    GEMM_MAIN(g_oh, g_woh)

#pragma unroll
    for (int mf = 0; mf < 2; mf++) {
        const int rl = wm * 32 + mf * 16 + qr;
        const int r0 = m0 + rl;
        const float s0 = rs_s[rl], s1 = rs_s[rl + 8];
#pragma unroll
        for (int nf = 0; nf < 8; nf++) {
            const int c0 = n0 + wn * 64 + nf * 8 + qc * 2;
            *(float2*)&out[(size_t)r0 * 1024 + c0] =
                make_float2(acc[mf][nf][0] * s0, acc[mf][nf][1] * s0);
            *(float2*)&out[(size_t)(r0 + 8) * 1024 + c0] =
                make_float2(acc[mf][nf][2] * s1, acc[mf][nf][3] * s1);
        }
    }
}

// ---------------------------------------------------------------------------
// Segmented KV scan (2 segments of 64 chunks): per (e-slice, d-slice, bh, seg)
// CTA keeps the 64x64 f32 state in mma accumulators (256 threads, warps
// 2(d)x4(e), warp tile 32x16). Seg 1 first sum-only accumulates chunks 0..63,
// then scans its segment. RACE-FIX: reloads are issued only after a
// __syncthreads() that follows all LDSM reads of the buffer being recycled
// (2 CTAs/SM warp skew can exceed cp.async landing latency).
// grid (2, 4, 32): z = bh*2 + seg.
// ---------------------------------------------------------------------------
#define KP_ROW 144                    // 72 halves per smem row
#define KP_V   (64*KP_ROW)            // 9216: v slice offset within stage
#define KP_STG (2*64*KP_ROW)          // 18432 per stage
#define KP_SS0 (4*KP_STG)             // 73728
#define KP_SS1 (KP_SS0 + 64*KP_ROW)   // 82944
#define KP_SMEM (KP_SS1 + 64*KP_ROW)  // 92160

__global__ __launch_bounds__(256) void kvscan_kernel()
{
    extern __shared__ char smc[];
    const uint32_t sb = smem_u32(smc);
    const int e0 = blockIdx.x * 64, d0 = blockIdx.y * 64;
    const int zz = blockIdx.z;
    const int seg = zz & 1, bh = zz >> 1;
    const int b = bh >> 3, h = bh & 7;
    const int tid = threadIdx.x, wid = tid >> 5, lane = tid & 31;
    const int wm = wid & 1, wn = wid >> 1;
    const int g = lane >> 2, t4 = lane & 3;
    const int lr = tid >> 3, lp = tid & 7;    // loader: row base, 16B col

    const uint32_t ca = (lane & 7) + ((lane >> 4) & 1) * 8;
    const uint32_t ma = ((lane >> 3) & 1) * 8;
    const uint32_t cb = (lane & 7) + ((lane >> 3) & 1) * 8;
    const uint32_t nb = (lane >> 4) * 8;

    const int c_begin = seg * 64;
    const int c_end   = c_begin + 64;

    float acc[2][2][4];
#pragma unroll
    for (int mf = 0; mf < 2; mf++)
#pragma unroll
        for (int nf = 0; nf < 2; nf++)
#pragma unroll
            for (int i = 0; i < 4; i++) acc[mf][nf][i] = 0.f;

#define KP_LOAD(c, st) {                                                       \
    uint32_t base = sb + (st) * KP_STG;                                        \
    const int tt = (c) * 64;                                                   \
    _Pragma("unroll")                                                          \
    for (int i = 0; i < 2; i++) {                                              \
        int r = lr + 32 * i;                                                   \
        cp16(base + (uint32_t)r * KP_ROW + lp * 16,                            \
             &g_kf[((size_t)(b*Tc + tt + r) * Hc + h) * Fc + d0 + lp * 8]);    \
        cp16(base + KP_V + (uint32_t)r * KP_ROW + lp * 16,                     \
             &g_v[(size_t)(b*Tc + tt + r) * HIDc + h * 128 + e0 + lp * 8]);    \
    } }

#define KP_STAGE(off) {                                                        \
    _Pragma("unroll")                                                          \
    for (int mf = 0; mf < 2; mf++)                                             \
        _Pragma("unroll")                                                      \
        for (int nf = 0; nf < 2; nf++) {                                       \
            int d = wm * 32 + mf * 16 + g;                                     \
            int e = wn * 16 + nf * 8 + t4 * 2;                                 \
            *(uint32_t*)(smc + (off) + ((uint32_t)d * KP_ROW + e * 2)) =       \
                pack2(acc[mf][nf][0], acc[mf][nf][1]);                         \
            *(uint32_t*)(smc + (off) + ((uint32_t)(d + 8) * KP_ROW + e * 2)) = \
                pack2(acc[mf][nf][2], acc[mf][nf][3]);                         \
        } }

#define KP_MMA(st) {                                                           \
    const uint32_t kfb = sb + (st) * KP_STG;                                   \
    const uint32_t vb  = kfb + KP_V;                                           \
    _Pragma("unroll")                                                          \
    for (int ks = 0; ks < 4; ks++) {                                           \
        uint32_t bbf[4];                                                       \
        LDSM4T(bbf, vb + ((ks*16 + cb) * KP_ROW + (wn*16 + nb) * 2));          \
        _Pragma("unroll")                                                      \
        for (int mf = 0; mf < 2; mf++) {                                       \
            uint32_t a[4];                                                     \
            LDSM4T(a, kfb + ((ks*16 + ca) * KP_ROW + (wm*32 + mf*16 + ma) * 2)); \
            mma_f16(acc[mf][0], a, bbf);                                       \
            mma_f16(acc[mf][1], a, bbf + 2);                                   \
        }                                                                      \
    } }

    KP_LOAD(0, 0); KP_LOAD(1, 1); CP_COMMIT();
    KP_LOAD(2, 2); KP_LOAD(3, 3); CP_COMMIT();

    const size_t sseq = ((size_t)bh) * NCc * (size_t)(Fc * Dc);

    // phase 1 (seg 1 only): sum-only accumulation of chunks [0, c_begin)
    for (int c = 0; c < c_begin; c += 2) {
        CP_WAIT(1);
        __syncthreads();       // pair (c, c+1) buffers landed
        KP_MMA(c & 3)
        KP_MMA((c + 1) & 3)
        __syncthreads();       // ALL warps done reading before recycle
        KP_LOAD(c + 4, (c + 4) & 3); KP_LOAD(c + 5, (c + 5) & 3);
        CP_COMMIT();
    }

    // phase 2: scan chunks [c_begin, c_end), writing exclusive S
    for (int c = c_begin; c < c_end; c += 2) {
        CP_WAIT(1);
        __syncthreads();       // pair buffers landed; prior SS reads done

        KP_STAGE(KP_SS0)       // exclusive state for chunk c
        KP_MMA(c & 3)          // state += chunk c
        KP_STAGE(KP_SS1)       // exclusive state for chunk c+1
        KP_MMA((c + 1) & 3)    // state += chunk c+1

        __syncthreads();       // reads of recycled buffers + SS staging done

        if (c + 4 < c_end) { KP_LOAD(c + 4, (c + 4) & 3); KP_LOAD(c + 5, (c + 5) & 3); }
        CP_COMMIT();

        const size_t sb0 = sseq + (size_t)c * (Fc * Dc);
        const size_t sb1 = sb0 + (size_t)(Fc * Dc);
#pragma unroll
        for (int i = 0; i < 2; i++) {
            int r = lr + 32 * i;
            *(uint4*)(&g_s[sb0 + (size_t)(d0 + r) * 128 + e0 + lp * 8]) =
                *(const uint4*)(smc + KP_SS0 + (uint32_t)r * KP_ROW + lp * 16);
            *(uint4*)(&g_s[sb1 + (size_t)(d0 + r) * 128 + e0 + lp * 8]) =
                *(const uint4*)(smc + KP_SS1 + (uint32_t)r * KP_ROW + lp * 16);
        }
    }
#undef KP_LOAD
#undef KP_STAGE
#undef KP_MMA
}

// ---------------------------------------------------------------------------
// Output per chunk (fp16 mma): o = tril(qf @ kf^T) @ v + qf @ S  -> fp16
// Front loads via cp.async. S streamed in 4x64-row quarters, double-buffered
// in the dead kf region. o staged through v buffer for coalesced stores +
// per-token sumsq partials. 2 CTAs/SM.
// ---------------------------------------------------------------------------
#define OQF 0
#define OKF 33792                     // kf (64x264) / S quarter bufs (2 x 64x136)
#define OSQ(i) (OKF + (i)*17408)
#define OV  68608                     // v (64x136) / o staging (64x136)
#define OAT 86016
#define OUT_SMEM 95232

__global__ __launch_bounds__(256, 2) void out_kernel()
{
    extern __shared__ char smc[];
    const uint32_t sb = smem_u32(smc);
    const int chunk = blockIdx.x, h = blockIdx.y, b = blockIdx.z;
    const int tid = threadIdx.x, wid = tid >> 5, lane = tid & 31;
    const int g = lane >> 2, t4 = lane & 3;
    const int t0 = chunk * 64;
    const int wm = wid & 1, wn = wid >> 1;

    const size_t qbase = ((size_t)(b*Tc + t0) * Hc + h) * Fc;
#pragma unroll
    for (int i = 0; i < 8; i++) {
        int l = tid + i * 256;
        int r = l >> 5, p = l & 31;
        size_t gs = qbase + (size_t)r * (Hc*Fc) + p * 8;
        cp16(sb + OQF + ((uint32_t)r * 264 + p * 8) * 2, &g_qf[gs]);
        cp16(sb + OKF + ((uint32_t)r * 264 + p * 8) * 2, &g_kf[gs]);
    }
#pragma unroll
    for (int i = 0; i < 4; i++) {
        int l = tid + i * 256;
        int r = l >> 4, p = l & 15;
        cp16(sb + OV + ((uint32_t)r * 136 + p * 8) * 2,
             &g_v[(size_t)(b*Tc + t0 + r) * HIDc + h * 128 + p * 8]);
    }
    CP_COMMIT(); CP_WAIT(0);
    __syncthreads();

    // phase 1: scores = tril(qf @ kf^T)
    {
        float sc[2][2][4];
#pragma unroll
        for (int mf = 0; mf < 2; mf++)
#pragma unroll
            for (int nf = 0; nf < 2; nf++)
#pragma unroll
                for (int i = 0; i < 4; i++) sc[mf][nf][i] = 0.f;

        const uint32_t aoff = OQF + (uint32_t)(wm*32 + (lane&7) + ((lane>>3)&1)*8) * 528
                            + (lane>>4)*16;
        const uint32_t boff = OKF + (uint32_t)(wn*16 + (lane>>4)*8 + (lane&7)) * 528
                            + ((lane>>3)&1)*16;
#pragma unroll
        for (int ks = 0; ks < 16; ks++) {
            uint32_t a[2][4], bbf[4];
            LDSM4(a[0], sb + aoff + ks * 32);
            LDSM4(a[1], sb + aoff + 16 * 528 + ks * 32);
            LDSM4(bbf, sb + boff + ks * 32);
            mma_f16(sc[0][0], a[0], bbf);
            mma_f16(sc[0][1], a[0], bbf + 2);
            mma_f16(sc[1][0], a[1], bbf);
            mma_f16(sc[1][1], a[1], bbf + 2);
        }
#pragma unroll
        for (int mf = 0; mf < 2; mf++)
#pragma unroll
            for (int nf = 0; nf < 2; nf++) {
                int ci = wm*32 + mf*16 + g;
                int cj = wn*16 + nf*8 + t4*2;
                float v0 = (cj     <= ci) ? sc[mf][nf][0] : 0.f;
                float v1 = (cj + 1 <= ci) ? sc[mf][nf][1] : 0.f;
                *(uint32_t*)(smc + OAT + ((uint32_t)ci * 72 + cj) * 2) = pack2(v0, v1);
                int ci2 = ci + 8;
                float v2 = (cj     <= ci2) ? sc[mf][nf][2] : 0.f;
                float v3 = (cj + 1 <= ci2) ? sc[mf][nf][3] : 0.f;
                *(uint32_t*)(smc + OAT + ((uint32_t)ci2 * 72 + cj) * 2) = pack2(v2, v3);
            }
    }
    __syncthreads();

    // phase 2: o = attn @ v + qf @ S, S in 4 quarters double-buffered
    const size_t sbase = (((size_t)(b*Hc + h)) * NCc + chunk) * (size_t)(Fc * Dc);
    float o[2][4][4];
#pragma unroll
    for (int mf = 0; mf < 2; mf++)
#pragma unroll
        for (int nf = 0; nf < 4; nf++)
#pragma unroll
            for (int i = 0; i < 4; i++) o[mf][nf][i] = 0.f;

    const uint32_t cb = (lane & 7) + ((lane >> 3) & 1) * 8;
    const uint32_t nb = (lane >> 4) * 8;
    const uint32_t a2 = OQF + (uint32_t)(wm*32 + (lane&7) + ((lane>>3)&1)*8) * 528
                      + (lane>>4)*16;

#pragma unroll
    for (int qq = 0; qq < 2; qq++) {
#pragma unroll
        for (int i = 0; i < 4; i++) {
            int l = tid + i * 256;
            int f = l >> 4, p = l & 15;
            cp16(sb + OSQ(qq) + ((uint32_t)f * 136 + p * 8) * 2,
                 &g_s[sbase + (size_t)(qq * 64 + f) * 128 + p * 8]);
        }
        CP_COMMIT();
    }

    // attn @ v (independent of S; overlaps S loads)
    {
        const uint32_t a1 = OAT + (uint32_t)(wm*32 + (lane&7) + ((lane>>3)&1)*8) * 144
                          + (lane>>4)*16;
#pragma unroll
        for (int ks = 0; ks < 4; ks++) {
            uint32_t a[2][4];
            LDSM4(a[0], sb + a1 + ks * 32);
            LDSM4(a[1], sb + a1 + 16 * 144 + ks * 32);
#pragma unroll
            for (int np = 0; np < 2; np++) {
                uint32_t bbf[4];
                LDSM4T(bbf, sb + OV + ((ks*16 + cb) * 136 + wn*32 + np*16 + nb) * 2);
                mma_f16(o[0][2*np],   a[0], bbf);
                mma_f16(o[0][2*np+1], a[0], bbf + 2);
                mma_f16(o[1][2*np],   a[1], bbf);
                mma_f16(o[1][2*np+1], a[1], bbf + 2);
            }
        }
    }

#pragma unroll
    for (int qq = 0; qq < 4; qq++) {
        if (qq < 3) { CP_WAIT(1); } else { CP_WAIT(0); }
        __syncthreads();
        const uint32_t sq = sb + OSQ(qq & 1);
#pragma unroll
        for (int kss = 0; kss < 4; kss++) {
            const int ks = qq * 4 + kss;
            uint32_t a[2][4];
            LDSM4(a[0], sb + a2 + ks * 32);
            LDSM4(a[1], sb + a2 + 16 * 528 + ks * 32);
#pragma unroll
            for (int np = 0; np < 2; np++) {
                uint32_t bbf[4];
                LDSM4T(bbf, sq + ((kss*16 + cb) * 136 + wn*32 + np*16 + nb) * 2);
                mma_f16(o[0][2*np],   a[0], bbf);
                mma_f16(o[0][2*np+1], a[0], bbf + 2);
                mma_f16(o[1][2*np],   a[1], bbf);
                mma_f16(o[1][2*np+1], a[1], bbf + 2);
            }
        }
        __syncthreads();
        if (qq + 2 < 4) {
#pragma unroll
            for (int i = 0; i < 4; i++) {
                int l = tid + i * 256;
                int f = l >> 4, p = l & 15;
                cp16(sb + OSQ(qq & 1) + ((uint32_t)f * 136 + p * 8) * 2,
                     &g_s[sbase + (size_t)((qq + 2) * 64 + f) * 128 + p * 8]);
            }
            CP_COMMIT();
        }
    }

    // stage o through the dead v buffer, then coalesced 16B writes + sumsq
#pragma unroll
    for (int mf = 0; mf < 2; mf++)
#pragma unroll
        for (int nf = 0; nf < 4; nf++) {
            int r = wm*32 + mf*16 + g;
            int e = wn*32 + nf*8 + t4*2;
            *(uint32_t*)(smc + OV + ((uint32_t)r * 136 + e) * 2) =
                pack2(o[mf][nf][0], o[mf][nf][1]);
            *(uint32_t*)(smc + OV + ((uint32_t)(r + 8) * 136 + e) * 2) =
                pack2(o[mf][nf][2], o[mf][nf][3]);
        }
    __syncthreads();
#pragma unroll
    for (int i = 0; i < 4; i++) {
        int l = tid + i * 256;
        int r = l >> 4, p = l & 15;
        *(uint4*)(&g_oh[(size_t)(b*Tc + t0 + r) * HIDc + h * 128 + p * 8]) =
            *(const uint4*)(smc + OV + ((uint32_t)r * 136 + p * 8) * 2);
    }

    // per-token sumsq partial (rmsnorm): 4 threads per token, 32 dims each
    {
        const int r = tid >> 2, part = tid & 3;
        float s = 0.f;
        const __half2* row = (const __half2*)(smc + OV + (uint32_t)r * 136 * 2);
#pragma unroll
        for (int j = 0; j < 16; j++) {
            float2 v = __half22float2(row[part * 16 + j]);
            s += v.x * v.x + v.y * v.y;
        }
        s += __shfl_xor_sync(0xffffffffu, s, 1);
        s += __shfl_xor_sync(0xffffffffu, s, 2);
        if (part == 0)
            g_prs[(size_t)(b*Tc + t0 + r) * Hc + h] = s;
    }
}

// ---------------------------------------------------------------------------
// Launch
// ---------------------------------------------------------------------------
extern "C" void kernel_launch(void* const* d_in, const int* in_sizes, int n_in,
                              void* d_out, int out_size)
{
    const float* x    = (const float*)d_in[0];
    const float* Wq   = (const float*)d_in[1];
    const float* Wk   = (const float*)d_in[2];
    const float* Wv   = (const float*)d_in[3];
    const float* Wo   = (const float*)d_in[4];
    const float* fmqw = (const float*)d_in[5];
    const float* fmqb = (const float*)d_in[6];
    const float* fmkw = (const float*)d_in[7];
    const float* fmkb = (const float*)d_in[8];
    float* out = (float*)d_out;

    cudaFuncSetAttribute(gemm_qkv,  cudaFuncAttributeMaxDynamicSharedMemorySize, GEMM_SMEM);
    cudaFuncSetAttribute(gemm_o,    cudaFuncAttributeMaxDynamicSharedMemorySize, GEMM_SMEM);
    cudaFuncSetAttribute(fold_w,    cudaFuncAttributeMaxDynamicSharedMemorySize, FOLD_SMEM);
    cudaFuncSetAttribute(kvscan_kernel, cudaFuncAttributeMaxDynamicSharedMemorySize, KP_SMEM);
    cudaFuncSetAttribute(out_kernel,cudaFuncAttributeMaxDynamicSharedMemorySize, OUT_SMEM);

    // conversions (x, Wv, Wo fused) + weight folding
    conv_all<<<9216, 256>>>(x, Wv, Wo);
    fold_w<<<dim3(8, 8, 2), 256, FOLD_SMEM>>>(fmqw, fmkw, Wq, Wk);

    // fused QKV GEMM + hedgehog softmax epilogue
    gemm_qkv<<<dim3(HIDc/128, MTOT/128, 3), 256, GEMM_SMEM>>>(fmqb, fmkb);

    // segmented KV scan (2 segments per (bh, d, e) tile; state in registers)
    kvscan_kernel<<<dim3(2, 4, Bc*Hc*2), 256, KP_SMEM>>>();

    out_kernel<<<dim3(NCc, Hc, Bc), 256, OUT_SMEM>>>();

    gemm_o<<<dim3(HIDc/128, MTOT/128, 1), 256, GEMM_SMEM>>>(out);
}